// round 16
// baseline (speedup 1.0000x reference)
#include <cuda_runtime.h>
#include <cuda_bf16.h>
#include <cstdint>

// ---------------------------------------------------------------------------
// BidirectionalAttention2 via mma.sync bf16x3 (sm_100-safe).
// Query + key compaction (masked keys -> constant weight c = exp(MASK_FILL-M0),
// via precomputed masked-row sums in fp32 at the epilogue).
// This round: revert R14's zero-unit CTAs (they reserved full SMEM and
// displaced compute CTAs); instead the qb==0 compute CTA zero-fills its
// (pass,b) masked rows, overlapped with its own cp.async staging.
// 4 launches: build_idx (fused dtype detect), cvt, msum, fa.
// ---------------------------------------------------------------------------

namespace {
constexpr int kB = 64;
constexpr int kL = 1024;
constexpr int kD = 256;
constexpr int BM = 128;
constexpr int BN = 32;
constexpr float MASK_FILL = -1e-07f;
constexpr float M0 = 44.0f;              // fixed softmax shift

constexpr int QCH = BM * 128;            // 16384 B per 64-col chunk
constexpr int KCH = BN * 128;            // 4096
constexpr int OFF_QHI = 0;
constexpr int OFF_QLO = 4 * QCH;         // 65536
constexpr int OFF_K   = 8 * QCH;         // 131072
constexpr int KBUF    = 8 * KCH;         // 32768 (hi ch0-3, lo ch4-7)
constexpr int AL_BYTES = OFF_K + 2 * KBUF;  // 196608
constexpr int CTRL = 4096;               // rowmap @0 (512B), skidx @1024 (2KB)
constexpr int SMEM_BYTES = AL_BYTES + CTRL + 1024;

constexpr size_t NEL = (size_t)2 * kB * kL * kD;   // both sides
}  // namespace

// ---------------- device globals ----------------
__device__ int g_cnt[2 * kB];                     // unmasked rows per (side,b)
__device__ unsigned short g_idx[2 * kB * kL];     // compacted unmasked rows
__device__ unsigned short g_midx[2 * kB * kL];    // compacted MASKED rows
__device__ float g_msum[2 * kB * kD];             // sum of masked rows of v_side
__device__ unsigned short g_hi[NEL];              // bf16 hi, [side][b][l][d]
__device__ unsigned short g_lo[NEL];              // bf16 lo residual

// ---------------- helpers ----------------
__device__ __forceinline__ uint32_t smem_u32(const void* p) {
    uint32_t a;
    asm("{ .reg .u64 t; cvta.to.shared.u64 t, %1; cvt.u32.u64 %0, t; }" : "=r"(a) : "l"(p));
    return a;
}
__device__ __forceinline__ uint32_t swzb(int r, int c) {
    return (uint32_t)(r * 128) + (uint32_t)((c * 2) ^ ((r & 7) << 4));
}
__device__ __forceinline__ void ldsm4(uint32_t* r, uint32_t addr) {
    asm volatile("ldmatrix.sync.aligned.m8n8.x4.shared.b16 {%0,%1,%2,%3}, [%4];"
                 : "=r"(r[0]), "=r"(r[1]), "=r"(r[2]), "=r"(r[3]) : "r"(addr));
}
__device__ __forceinline__ void ldsm4t(uint32_t* r, uint32_t addr) {
    asm volatile("ldmatrix.sync.aligned.m8n8.x4.trans.shared.b16 {%0,%1,%2,%3}, [%4];"
                 : "=r"(r[0]), "=r"(r[1]), "=r"(r[2]), "=r"(r[3]) : "r"(addr));
}
__device__ __forceinline__ void mma16816(float* c, const uint32_t* a, const uint32_t* b) {
    asm volatile("mma.sync.aligned.m16n8k16.row.col.f32.bf16.bf16.f32 "
                 "{%0,%1,%2,%3}, {%4,%5,%6,%7}, {%8,%9}, {%0,%1,%2,%3};"
                 : "+f"(c[0]), "+f"(c[1]), "+f"(c[2]), "+f"(c[3])
                 : "r"(a[0]), "r"(a[1]), "r"(a[2]), "r"(a[3]), "r"(b[0]), "r"(b[1]));
}
__device__ __forceinline__ bool load_mask(const void* m, int i, int mode) {
    if (mode == 0) return ((const unsigned char*)m)[i] != 0;
    if (mode == 1) return ((const int*)m)[i] != 0;
    return ((const float*)m)[i] != 0.0f;
}
#define CP_ASYNC16(dst, src) \
    asm volatile("cp.async.cg.shared.global [%0], [%1], 16;" \
                 :: "r"(dst), "l"(src) : "memory")
#define CP_COMMIT() asm volatile("cp.async.commit_group;" ::: "memory")
#define CP_WAIT0()  asm volatile("cp.async.wait_group 0;"  ::: "memory")

// ---------------- prologue kernels ----------------
// one warp per (side, b): detect mask dtype from the SAME leading 16KB of v1m
// (identical data -> identical mode in every block), then deterministic
// ballot compaction of unmasked AND masked row index lists.
__global__ void build_idx_kernel(const void* __restrict__ v1m,
                                 const void* __restrict__ v2m) {
    const int lane = threadIdx.x;

    const unsigned int* mw = (const unsigned int*)v1m;
    int bi = 0, bf = 0;
    for (int i = lane; i < 4096; i += 32) {
        unsigned int wv = mw[i];
        if (wv > 1u) bi = 1;
        if (wv != 0u && wv != 0x3f800000u) bf = 1;
    }
    bi = __any_sync(0xffffffffu, bi);
    bf = __any_sync(0xffffffffu, bf);
    const int mode = (!bi) ? 1 : ((!bf) ? 2 : 0);

    const int pb = blockIdx.x;            // 0..127
    const int side = pb >> 6, b = pb & 63;
    const void* qm = side ? v2m : v1m;
    int cnt = 0, mcnt = 0;
    for (int i0 = 0; i0 < kL; i0 += 32) {
        int i = i0 + lane;
        bool masked = load_mask(qm, b * kL + i, mode);
        unsigned balK = __ballot_sync(0xffffffffu, !masked);
        unsigned prefix = (1u << lane) - 1u;
        if (!masked) g_idx [pb * kL + cnt  + __popc(balK  & prefix)] = (unsigned short)i;
        else         g_midx[pb * kL + mcnt + __popc(~balK & prefix)] = (unsigned short)i;
        cnt  += __popc(balK);
        mcnt += 32 - __popc(balK);
    }
    if (lane == 0) g_cnt[pb] = cnt;
}

// fp32 -> bf16 hi/lo for UNMASKED rows only. grid = 2*kB*16.
__global__ void cvt_kernel(const float* __restrict__ v1,
                           const float* __restrict__ v2) {
    const int blk = blockIdx.x;
    const int pb = blk >> 4, part = blk & 15;
    const int side = pb >> 6, b = pb & 63;
    const int cnt = g_cnt[pb];
    const float* src = (side ? v2 : v1) + (size_t)b * kL * kD;
    const size_t dst0 = ((size_t)side * kB + b) * kL * kD;
    const unsigned short* rows = g_idx + (size_t)pb * kL;
    const int r0 = part * 64;
    for (int i = threadIdx.x; i < 64 * 64; i += 256) {     // 64 rows x 64 f4
        int rr = r0 + (i >> 6);
        if (rr >= cnt) break;
        int row = (int)rows[rr];
        int c4 = i & 63;
        float4 v = *(const float4*)(src + (size_t)row * kD + (c4 << 2));
        __nv_bfloat162 h0 = __float22bfloat162_rn(make_float2(v.x, v.y));
        __nv_bfloat162 h1 = __float22bfloat162_rn(make_float2(v.z, v.w));
        float2 l0f = make_float2(v.x - __bfloat162float(h0.x), v.y - __bfloat162float(h0.y));
        float2 l1f = make_float2(v.z - __bfloat162float(h1.x), v.w - __bfloat162float(h1.y));
        __nv_bfloat162 l0 = __float22bfloat162_rn(l0f);
        __nv_bfloat162 l1 = __float22bfloat162_rn(l1f);
        size_t o = dst0 + (size_t)row * kD + (c4 << 2);
        *(uint2*)(g_hi + o) = make_uint2(*(uint32_t*)&h0, *(uint32_t*)&h1);
        *(uint2*)(g_lo + o) = make_uint2(*(uint32_t*)&l0, *(uint32_t*)&l1);
    }
}

// grid 512 = (side,b) x 4 column chunks, 512 threads (8 row groups):
// fp32 sum of MASKED rows of v_side (deterministic tree reduce).
__global__ void msum_kernel(const float* __restrict__ v1,
                            const float* __restrict__ v2) {
    const int blk = blockIdx.x;
    const int pb = blk >> 2, cc = blk & 3;
    const int side = pb >> 6, b = pb & 63;
    const float* vals = (side ? v2 : v1) + (size_t)b * kL * kD;
    const int mcnt = kL - g_cnt[pb];
    const unsigned short* mrows = g_midx + (size_t)pb * kL;
    const int col = cc * 64 + (threadIdx.x & 63);
    const int rg  = threadIdx.x >> 6;     // 0..7
    __shared__ float red[8][64];
    float acc = 0.0f;
    for (int j = rg; j < mcnt; j += 8)
        acc += vals[(size_t)mrows[j] * kD + col];
    red[rg][threadIdx.x & 63] = acc;
    __syncthreads();
    if (rg == 0) {
        float s = 0.0f;
#pragma unroll
        for (int k = 0; k < 8; ++k) s += red[k][threadIdx.x & 63];
        g_msum[pb * kD + col] = s;
    }
}

// ---------------- main kernel ----------------
__global__ __launch_bounds__(256, 1)
void fa_mma_kernel(float* __restrict__ out)
{
    extern __shared__ char sm[];
    const uint32_t raw = smem_u32(sm);
    const uint32_t al  = (raw + CTRL + 1023u) & ~1023u;
    int* rowmap = (int*)sm;                              // 128 ints
    unsigned short* skidx = (unsigned short*)(sm + 1024); // 1024 ushorts

    const int tid  = threadIdx.x;
    const int lane = tid & 31;
    const int w    = tid >> 5;
    const int pass = blockIdx.z;
    const int b    = blockIdx.y;
    const int qb   = blockIdx.x;             // 0..7
    const int pb   = pass * kB + b;          // query side index
    const int kpb  = (1 - pass) * kB + b;    // key side index

    const int cnt = g_cnt[pb];

    // ---- qb==0 CTA also zero-fills this (pass,b)'s masked query rows.
    //      Issued before staging; STGs drain under cp.async/MMA. ----
    if (qb == 0) {
        const int mcnt = kL - cnt;
        const unsigned short* mrows = g_midx + (size_t)pb * kL;
        float4* OB = (float4*)(out + ((size_t)pass * kB + b) * kL * kD);
        const float4 z = make_float4(0.0f, 0.0f, 0.0f, 0.0f);
        for (int i = tid; i < mcnt * 64; i += 256)
            OB[(size_t)mrows[i >> 6] * 64 + (i & 63)] = z;
    }

    const int base = qb * BM;
    if (base >= cnt) return;
    const int nact = min(BM, cnt - base);

    const int kcnt   = g_cnt[kpb];
    const int ktiles = (kcnt + BN - 1) / BN;
    const int kclamp = max(kcnt - 1, 0);

    const size_t qoff = ((size_t)pass * kB + b) * kL * kD;
    const size_t koff = ((size_t)(1 - pass) * kB + b) * kL * kD;

    if (tid < BM) {
        int s = base + tid;
        rowmap[tid] = (int)g_idx[pb * kL + (s < cnt ? s : base)];
    }
    for (int i = tid; i < kL; i += 256)
        skidx[i] = g_idx[(size_t)kpb * kL + i];
    __syncthreads();

    // ---- group 0: Q tile (gathered, swizzled dst) + key tile 0 ----
    {
#pragma unroll
        for (int g16 = 0; g16 < 16; ++g16) {           // Q hi+lo
            int g = tid + 256 * g16;                   // 0..4095
            int r = g >> 5, gcol = (g & 31) * 8;
            uint32_t d = (uint32_t)((gcol >> 6) * QCH) + swzb(r, gcol & 63);
            size_t s = qoff + (size_t)rowmap[r] * kD + gcol;
            CP_ASYNC16(al + OFF_QHI + d, (const char*)(g_hi + s));
            CP_ASYNC16(al + OFF_QLO + d, (const char*)(g_lo + s));
        }
#pragma unroll
        for (int g4 = 0; g4 < 4; ++g4) {               // K tile 0 hi+lo
            int g = tid + 256 * g4;                    // 0..1023
            int r = g >> 5, gcol = (g & 31) * 8;
            int slot = min(r, kclamp);
            uint32_t d = (uint32_t)((gcol >> 6) * KCH) + swzb(r, gcol & 63);
            size_t s = koff + (size_t)skidx[slot] * kD + gcol;
            CP_ASYNC16(al + OFF_K + d,           (const char*)(g_hi + s));
            CP_ASYNC16(al + OFF_K + 4 * KCH + d, (const char*)(g_lo + s));
        }
        CP_COMMIT();
    }

    // fragment coordinates
    const int a_row = 16 * w + (lane & 15);
    const int a_dh  = (lane >> 4) * 8;
    const int b_key = (lane & 7) + ((lane >> 4) & 1) * 8;
    const int b_dh  = ((lane >> 3) & 1) * 8;
    const int v_key = (lane & 7) + ((lane >> 3) & 1) * 8;
    const int v_dh  = ((lane >> 4) & 1) * 8;

    float oac[32][4];
#pragma unroll
    for (int i = 0; i < 32; ++i)
#pragma unroll
        for (int j = 0; j < 4; ++j) oac[i][j] = 0.0f;
    float lp0 = 0.0f, lp1 = 0.0f;

#pragma unroll 1
    for (int t = 0; t < ktiles; ++t) {
        const uint32_t kb = al + OFF_K + (t & 1) * KBUF;

        // ---- tile t arrived; single barrier also retires WAR on buf t-1 ----
        CP_WAIT0();
        __syncthreads();

        // ---- issue copy of tile t+1 (overlaps full MMA body below) ----
        if (t + 1 < ktiles) {
            const uint32_t kbn = al + OFF_K + ((t + 1) & 1) * KBUF;
#pragma unroll
            for (int g4 = 0; g4 < 4; ++g4) {
                int g = tid + 256 * g4;
                int r = g >> 5, gcol = (g & 31) * 8;
                int slot = min((t + 1) * BN + r, kclamp);
                uint32_t d = (uint32_t)((gcol >> 6) * KCH) + swzb(r, gcol & 63);
                size_t s = koff + (size_t)skidx[slot] * kD + gcol;
                CP_ASYNC16(kbn + d,           (const char*)(g_hi + s));
                CP_ASYNC16(kbn + 4 * KCH + d, (const char*)(g_lo + s));
            }
            CP_COMMIT();
        }

        // ---- S = Q.K^T for tile t ----
        float sfr[4][4];
#pragma unroll
        for (int j = 0; j < 4; ++j)
#pragma unroll
            for (int c = 0; c < 4; ++c) sfr[j][c] = 0.0f;

#pragma unroll
        for (int ks = 0; ks < 16; ++ks) {
            uint32_t ahi[4], alo2[4];
            {
                int dd = 16 * ks + a_dh;
                uint32_t qo = (uint32_t)((dd >> 6) * QCH) + swzb(a_row, dd & 63);
                ldsm4(ahi, al + OFF_QHI + qo);
                ldsm4(alo2, al + OFF_QLO + qo);
            }
            uint32_t bh[2][4], bl[2][4];
#pragma unroll
            for (int u = 0; u < 2; ++u) {
                int key = 16 * u + b_key;
                int dd  = 16 * ks + b_dh;
                uint32_t ko = (uint32_t)((dd >> 6) * KCH) + swzb(key, dd & 63);
                ldsm4(bh[u], kb + ko);
                ldsm4(bl[u], kb + 4 * KCH + ko);
            }
#pragma unroll
            for (int u = 0; u < 2; ++u) {
                mma16816(sfr[2 * u],     ahi, bh[u]);
                mma16816(sfr[2 * u + 1], ahi, bh[u] + 2);
            }
#pragma unroll
            for (int u = 0; u < 2; ++u) {
                mma16816(sfr[2 * u],     ahi, bl[u]);
                mma16816(sfr[2 * u + 1], ahi, bl[u] + 2);
            }
#pragma unroll
            for (int u = 0; u < 2; ++u) {
                mma16816(sfr[2 * u],     alo2, bh[u]);
                mma16816(sfr[2 * u + 1], alo2, bh[u] + 2);
            }
        }

        // ---- softmax(t): real keys all unmasked; pad slots -> p = 0 ----
        uint32_t phi[2][4], plo[2][4];
#pragma unroll
        for (int kp = 0; kp < 2; ++kp) {
#pragma unroll
            for (int jj = 0; jj < 2; ++jj) {
                int j  = 2 * kp + jj;
                int n0 = 8 * j + 2 * (lane & 3);
                int slot0 = t * BN + n0;
                float s0 = sfr[j][0], s1 = sfr[j][1], s2 = sfr[j][2], s3 = sfr[j][3];
                if (slot0 >= kcnt)     { s0 = -1e30f; s2 = -1e30f; }
                if (slot0 + 1 >= kcnt) { s1 = -1e30f; s3 = -1e30f; }
                float p0 = __expf(s0 - M0), p1 = __expf(s1 - M0);
                float p2 = __expf(s2 - M0), p3 = __expf(s3 - M0);
                lp0 += p0 + p1;
                lp1 += p2 + p3;
                __nv_bfloat162 h01 = __float22bfloat162_rn(make_float2(p0, p1));
                __nv_bfloat162 h23 = __float22bfloat162_rn(make_float2(p2, p3));
                float2 r01 = make_float2(p0 - __bfloat162float(h01.x),
                                         p1 - __bfloat162float(h01.y));
                float2 r23 = make_float2(p2 - __bfloat162float(h23.x),
                                         p3 - __bfloat162float(h23.y));
                __nv_bfloat162 l01 = __float22bfloat162_rn(r01);
                __nv_bfloat162 l23 = __float22bfloat162_rn(r23);
                phi[kp][2 * jj]     = *(uint32_t*)&h01;
                phi[kp][2 * jj + 1] = *(uint32_t*)&h23;
                plo[kp][2 * jj]     = *(uint32_t*)&l01;
                plo[kp][2 * jj + 1] = *(uint32_t*)&l23;
            }
        }

        // ---- O += P(t).V(t) ----
#pragma unroll
        for (int kp = 0; kp < 2; ++kp) {
#pragma unroll
            for (int dpp = 0; dpp < 8; ++dpp) {
                uint32_t vh[2][4], vl[2][4];
#pragma unroll
                for (int u = 0; u < 2; ++u) {
                    int key = 16 * kp + v_key;
                    int dd  = 16 * (2 * dpp + u) + v_dh;
                    uint32_t vo = (uint32_t)((dd >> 6) * KCH) + swzb(key, dd & 63);
                    ldsm4t(vh[u], kb + vo);
                    ldsm4t(vl[u], kb + 4 * KCH + vo);
                }
#pragma unroll
                for (int u = 0; u < 2; ++u) {
                    int o = 2 * (2 * dpp + u);
                    mma16816(oac[o],     phi[kp], vh[u]);
                    mma16816(oac[o + 1], phi[kp], vh[u] + 2);
                }
#pragma unroll
                for (int u = 0; u < 2; ++u) {
                    int o = 2 * (2 * dpp + u);
                    mma16816(oac[o],     phi[kp], vl[u]);
                    mma16816(oac[o + 1], phi[kp], vl[u] + 2);
                }
#pragma unroll
                for (int u = 0; u < 2; ++u) {
                    int o = 2 * (2 * dpp + u);
                    mma16816(oac[o],     plo[kp], vh[u]);
                    mma16816(oac[o + 1], plo[kp], vh[u] + 2);
                }
            }
        }
    }

    // ---- epilogue: masked-key correction + normalize + scatter ----
    lp0 += __shfl_xor_sync(0xffffffffu, lp0, 1);
    lp0 += __shfl_xor_sync(0xffffffffu, lp0, 2);
    lp1 += __shfl_xor_sync(0xffffffffu, lp1, 1);
    lp1 += __shfl_xor_sync(0xffffffffu, lp1, 2);

    const float cmask = __expf(MASK_FILL - M0);
    const float mcntf = (float)(kL - kcnt);
    const float inv0 = 1.0f / (lp0 + cmask * mcntf);
    const float inv1 = 1.0f / (lp1 + cmask * mcntf);
    const float* ms = g_msum + (size_t)kpb * kD;

    const int lr0 = 16 * w + (lane >> 2);
    const int lr1 = lr0 + 8;

    float* OB = out + ((size_t)pass * kB + b) * kL * kD;
    if (lr0 < nact) {
        float* O0 = OB + (size_t)rowmap[lr0] * kD;
#pragma unroll
        for (int nt = 0; nt < 32; ++nt) {
            int d = 8 * nt + 2 * (lane & 3);
            float2 m2 = *(const float2*)(ms + d);
            *(float2*)(O0 + d) = make_float2((oac[nt][0] + cmask * m2.x) * inv0,
                                             (oac[nt][1] + cmask * m2.y) * inv0);
        }
    }
    if (lr1 < nact) {
        float* O1 = OB + (size_t)rowmap[lr1] * kD;
#pragma unroll
        for (int nt = 0; nt < 32; ++nt) {
            int d = 8 * nt + 2 * (lane & 3);
            float2 m2 = *(const float2*)(ms + d);
            *(float2*)(O1 + d) = make_float2((oac[nt][2] + cmask * m2.x) * inv1,
                                             (oac[nt][3] + cmask * m2.y) * inv1);
        }
    }
}

extern "C" void kernel_launch(void* const* d_in, const int* in_sizes, int n_in,
                              void* d_out, int out_size) {
    (void)in_sizes; (void)n_in; (void)out_size;
    const float* v1  = (const float*)d_in[0];
    const void*  v1m = d_in[1];
    const float* v2  = (const float*)d_in[2];
    const void*  v2m = d_in[3];
    float* out = (float*)d_out;

    cudaFuncSetAttribute(fa_mma_kernel,
                         cudaFuncAttributeMaxDynamicSharedMemorySize, SMEM_BYTES);

    build_idx_kernel<<<2 * kB, 32>>>(v1m, v2m);
    cvt_kernel<<<2 * kB * 16, 256>>>(v1, v2);
    msum_kernel<<<4 * 2 * kB, 512>>>(v1, v2);
    dim3 grid(kL / BM, kB, 2);
    fa_mma_kernel<<<grid, 256, SMEM_BYTES>>>(out);
}

// round 17
// speedup vs baseline: 1.0413x; 1.0413x over previous
#include <cuda_runtime.h>
#include <cuda_bf16.h>
#include <cstdint>

// ---------------------------------------------------------------------------
// BidirectionalAttention2 via mma.sync bf16x3 (sm_100-safe).
// Query + key compaction (masked keys -> constant weight c = exp(MASK_FILL-M0),
// via precomputed masked-row sums in fp32 at the epilogue).
// This round: exact R13 fa mainloop (zero work OUT of fa -- folding it in
// cost ~50us twice); msum and zero-fill fused into one launch (disjoint
// block ranges); detect fused in build_idx. 4 launches, fa profiled directly.
// ---------------------------------------------------------------------------

namespace {
constexpr int kB = 64;
constexpr int kL = 1024;
constexpr int kD = 256;
constexpr int BM = 128;
constexpr int BN = 32;
constexpr float MASK_FILL = -1e-07f;
constexpr float M0 = 44.0f;              // fixed softmax shift

constexpr int QCH = BM * 128;            // 16384 B per 64-col chunk
constexpr int KCH = BN * 128;            // 4096
constexpr int OFF_QHI = 0;
constexpr int OFF_QLO = 4 * QCH;         // 65536
constexpr int OFF_K   = 8 * QCH;         // 131072
constexpr int KBUF    = 8 * KCH;         // 32768 (hi ch0-3, lo ch4-7)
constexpr int AL_BYTES = OFF_K + 2 * KBUF;  // 196608
constexpr int CTRL = 4096;               // rowmap @0 (512B), skidx @1024 (2KB)
constexpr int SMEM_BYTES = AL_BYTES + CTRL + 1024;

constexpr size_t NEL = (size_t)2 * kB * kL * kD;   // both sides
}  // namespace

// ---------------- device globals ----------------
__device__ int g_cnt[2 * kB];                     // unmasked rows per (side,b)
__device__ unsigned short g_idx[2 * kB * kL];     // compacted unmasked rows
__device__ unsigned short g_midx[2 * kB * kL];    // compacted MASKED rows
__device__ float g_msum[2 * kB * kD];             // sum of masked rows of v_side
__device__ unsigned short g_hi[NEL];              // bf16 hi, [side][b][l][d]
__device__ unsigned short g_lo[NEL];              // bf16 lo residual

// ---------------- helpers ----------------
__device__ __forceinline__ uint32_t smem_u32(const void* p) {
    uint32_t a;
    asm("{ .reg .u64 t; cvta.to.shared.u64 t, %1; cvt.u32.u64 %0, t; }" : "=r"(a) : "l"(p));
    return a;
}
__device__ __forceinline__ uint32_t swzb(int r, int c) {
    return (uint32_t)(r * 128) + (uint32_t)((c * 2) ^ ((r & 7) << 4));
}
__device__ __forceinline__ void ldsm4(uint32_t* r, uint32_t addr) {
    asm volatile("ldmatrix.sync.aligned.m8n8.x4.shared.b16 {%0,%1,%2,%3}, [%4];"
                 : "=r"(r[0]), "=r"(r[1]), "=r"(r[2]), "=r"(r[3]) : "r"(addr));
}
__device__ __forceinline__ void ldsm4t(uint32_t* r, uint32_t addr) {
    asm volatile("ldmatrix.sync.aligned.m8n8.x4.trans.shared.b16 {%0,%1,%2,%3}, [%4];"
                 : "=r"(r[0]), "=r"(r[1]), "=r"(r[2]), "=r"(r[3]) : "r"(addr));
}
__device__ __forceinline__ void mma16816(float* c, const uint32_t* a, const uint32_t* b) {
    asm volatile("mma.sync.aligned.m16n8k16.row.col.f32.bf16.bf16.f32 "
                 "{%0,%1,%2,%3}, {%4,%5,%6,%7}, {%8,%9}, {%0,%1,%2,%3};"
                 : "+f"(c[0]), "+f"(c[1]), "+f"(c[2]), "+f"(c[3])
                 : "r"(a[0]), "r"(a[1]), "r"(a[2]), "r"(a[3]), "r"(b[0]), "r"(b[1]));
}
__device__ __forceinline__ bool load_mask(const void* m, int i, int mode) {
    if (mode == 0) return ((const unsigned char*)m)[i] != 0;
    if (mode == 1) return ((const int*)m)[i] != 0;
    return ((const float*)m)[i] != 0.0f;
}
#define CP_ASYNC16(dst, src) \
    asm volatile("cp.async.cg.shared.global [%0], [%1], 16;" \
                 :: "r"(dst), "l"(src) : "memory")
#define CP_COMMIT() asm volatile("cp.async.commit_group;" ::: "memory")
#define CP_WAIT0()  asm volatile("cp.async.wait_group 0;"  ::: "memory")

// ---------------- prologue kernels ----------------
// one warp per (side, b): detect mask dtype from the SAME leading 16KB of v1m
// (identical data -> identical mode in every block), then deterministic
// ballot compaction of unmasked AND masked row index lists.
__global__ void build_idx_kernel(const void* __restrict__ v1m,
                                 const void* __restrict__ v2m) {
    const int lane = threadIdx.x;

    const unsigned int* mw = (const unsigned int*)v1m;
    int bi = 0, bf = 0;
    for (int i = lane; i < 4096; i += 32) {
        unsigned int wv = mw[i];
        if (wv > 1u) bi = 1;
        if (wv != 0u && wv != 0x3f800000u) bf = 1;
    }
    bi = __any_sync(0xffffffffu, bi);
    bf = __any_sync(0xffffffffu, bf);
    const int mode = (!bi) ? 1 : ((!bf) ? 2 : 0);

    const int pb = blockIdx.x;            // 0..127
    const int side = pb >> 6, b = pb & 63;
    const void* qm = side ? v2m : v1m;
    int cnt = 0, mcnt = 0;
    for (int i0 = 0; i0 < kL; i0 += 32) {
        int i = i0 + lane;
        bool masked = load_mask(qm, b * kL + i, mode);
        unsigned balK = __ballot_sync(0xffffffffu, !masked);
        unsigned prefix = (1u << lane) - 1u;
        if (!masked) g_idx [pb * kL + cnt  + __popc(balK  & prefix)] = (unsigned short)i;
        else         g_midx[pb * kL + mcnt + __popc(~balK & prefix)] = (unsigned short)i;
        cnt  += __popc(balK);
        mcnt += 32 - __popc(balK);
    }
    if (lane == 0) g_cnt[pb] = cnt;
}

// fp32 -> bf16 hi/lo for UNMASKED rows only. grid = 2*kB*16.
__global__ void cvt_kernel(const float* __restrict__ v1,
                           const float* __restrict__ v2) {
    const int blk = blockIdx.x;
    const int pb = blk >> 4, part = blk & 15;
    const int side = pb >> 6, b = pb & 63;
    const int cnt = g_cnt[pb];
    const float* src = (side ? v2 : v1) + (size_t)b * kL * kD;
    const size_t dst0 = ((size_t)side * kB + b) * kL * kD;
    const unsigned short* rows = g_idx + (size_t)pb * kL;
    const int r0 = part * 64;
    for (int i = threadIdx.x; i < 64 * 64; i += 256) {     // 64 rows x 64 f4
        int rr = r0 + (i >> 6);
        if (rr >= cnt) break;
        int row = (int)rows[rr];
        int c4 = i & 63;
        float4 v = *(const float4*)(src + (size_t)row * kD + (c4 << 2));
        __nv_bfloat162 h0 = __float22bfloat162_rn(make_float2(v.x, v.y));
        __nv_bfloat162 h1 = __float22bfloat162_rn(make_float2(v.z, v.w));
        float2 l0f = make_float2(v.x - __bfloat162float(h0.x), v.y - __bfloat162float(h0.y));
        float2 l1f = make_float2(v.z - __bfloat162float(h1.x), v.w - __bfloat162float(h1.y));
        __nv_bfloat162 l0 = __float22bfloat162_rn(l0f);
        __nv_bfloat162 l1 = __float22bfloat162_rn(l1f);
        size_t o = dst0 + (size_t)row * kD + (c4 << 2);
        *(uint2*)(g_hi + o) = make_uint2(*(uint32_t*)&h0, *(uint32_t*)&h1);
        *(uint2*)(g_lo + o) = make_uint2(*(uint32_t*)&l0, *(uint32_t*)&l1);
    }
}

// Fused: blocks [0,512) = msum ((side,b) x 4 col chunks, 8 row groups);
//        blocks [512,1024) = zero-fill masked query rows via complement list.
__global__ void msum_zero_kernel(const float* __restrict__ v1,
                                 const float* __restrict__ v2,
                                 float* __restrict__ out) {
    const int blk = blockIdx.x;
    if (blk < 512) {
        const int pb = blk >> 2, cc = blk & 3;
        const int side = pb >> 6, b = pb & 63;
        const float* vals = (side ? v2 : v1) + (size_t)b * kL * kD;
        const int mcnt = kL - g_cnt[pb];
        const unsigned short* mrows = g_midx + (size_t)pb * kL;
        const int col = cc * 64 + (threadIdx.x & 63);
        const int rg  = threadIdx.x >> 6;     // 0..7
        __shared__ float red[8][64];
        float acc = 0.0f;
        for (int j = rg; j < mcnt; j += 8)
            acc += vals[(size_t)mrows[j] * kD + col];
        red[rg][threadIdx.x & 63] = acc;
        __syncthreads();
        if (rg == 0) {
            float s = 0.0f;
#pragma unroll
            for (int k = 0; k < 8; ++k) s += red[k][threadIdx.x & 63];
            g_msum[pb * kD + col] = s;
        }
    } else {
        const int z = blk - 512;
        const int pb = z >> 2, part = z & 3;
        const int pass = pb >> 6, b = pb & 63;
        const int mcnt = kL - g_cnt[pb];
        const unsigned short* mrows = g_midx + (size_t)pb * kL;
        float4* OB = (float4*)(out + ((size_t)pass * kB + b) * kL * kD);
        const float4 zv = make_float4(0.0f, 0.0f, 0.0f, 0.0f);
        const int count = (mcnt - part + 3) >> 2;   // rows j = part + 4*s
        for (int s = threadIdx.x; s < count * 64; s += blockDim.x) {
            int j = part + 4 * (s >> 6);
            OB[(size_t)mrows[j] * 64 + (s & 63)] = zv;
        }
    }
}

// ---------------- main kernel (identical to R13 mainloop) ----------------
__global__ __launch_bounds__(256, 1)
void fa_mma_kernel(float* __restrict__ out)
{
    extern __shared__ char sm[];
    const uint32_t raw = smem_u32(sm);
    const uint32_t al  = (raw + CTRL + 1023u) & ~1023u;
    int* rowmap = (int*)sm;                              // 128 ints
    unsigned short* skidx = (unsigned short*)(sm + 1024); // 1024 ushorts

    const int tid  = threadIdx.x;
    const int lane = tid & 31;
    const int w    = tid >> 5;
    const int pass = blockIdx.z;
    const int b    = blockIdx.y;
    const int qb   = blockIdx.x;             // 0..7
    const int pb   = pass * kB + b;          // query side index
    const int kpb  = (1 - pass) * kB + b;    // key side index

    const int cnt  = g_cnt[pb];
    const int base = qb * BM;
    if (base >= cnt) return;
    const int nact = min(BM, cnt - base);

    const int kcnt   = g_cnt[kpb];
    const int ktiles = (kcnt + BN - 1) / BN;
    const int kclamp = max(kcnt - 1, 0);

    const size_t qoff = ((size_t)pass * kB + b) * kL * kD;
    const size_t koff = ((size_t)(1 - pass) * kB + b) * kL * kD;

    if (tid < BM) {
        int s = base + tid;
        rowmap[tid] = (int)g_idx[pb * kL + (s < cnt ? s : base)];
    }
    for (int i = tid; i < kL; i += 256)
        skidx[i] = g_idx[(size_t)kpb * kL + i];
    __syncthreads();

    // ---- group 0: Q tile (gathered, swizzled dst) + key tile 0 ----
    {
#pragma unroll
        for (int g16 = 0; g16 < 16; ++g16) {           // Q hi+lo
            int g = tid + 256 * g16;                   // 0..4095
            int r = g >> 5, gcol = (g & 31) * 8;
            uint32_t d = (uint32_t)((gcol >> 6) * QCH) + swzb(r, gcol & 63);
            size_t s = qoff + (size_t)rowmap[r] * kD + gcol;
            CP_ASYNC16(al + OFF_QHI + d, (const char*)(g_hi + s));
            CP_ASYNC16(al + OFF_QLO + d, (const char*)(g_lo + s));
        }
#pragma unroll
        for (int g4 = 0; g4 < 4; ++g4) {               // K tile 0 hi+lo
            int g = tid + 256 * g4;                    // 0..1023
            int r = g >> 5, gcol = (g & 31) * 8;
            int slot = min(r, kclamp);
            uint32_t d = (uint32_t)((gcol >> 6) * KCH) + swzb(r, gcol & 63);
            size_t s = koff + (size_t)skidx[slot] * kD + gcol;
            CP_ASYNC16(al + OFF_K + d,           (const char*)(g_hi + s));
            CP_ASYNC16(al + OFF_K + 4 * KCH + d, (const char*)(g_lo + s));
        }
        CP_COMMIT();
    }

    // fragment coordinates
    const int a_row = 16 * w + (lane & 15);
    const int a_dh  = (lane >> 4) * 8;
    const int b_key = (lane & 7) + ((lane >> 4) & 1) * 8;
    const int b_dh  = ((lane >> 3) & 1) * 8;
    const int v_key = (lane & 7) + ((lane >> 3) & 1) * 8;
    const int v_dh  = ((lane >> 4) & 1) * 8;

    float oac[32][4];
#pragma unroll
    for (int i = 0; i < 32; ++i)
#pragma unroll
        for (int j = 0; j < 4; ++j) oac[i][j] = 0.0f;
    float lp0 = 0.0f, lp1 = 0.0f;

#pragma unroll 1
    for (int t = 0; t < ktiles; ++t) {
        const uint32_t kb = al + OFF_K + (t & 1) * KBUF;

        // ---- tile t arrived; single barrier also retires WAR on buf t-1 ----
        CP_WAIT0();
        __syncthreads();

        // ---- issue copy of tile t+1 (overlaps full MMA body below) ----
        if (t + 1 < ktiles) {
            const uint32_t kbn = al + OFF_K + ((t + 1) & 1) * KBUF;
#pragma unroll
            for (int g4 = 0; g4 < 4; ++g4) {
                int g = tid + 256 * g4;
                int r = g >> 5, gcol = (g & 31) * 8;
                int slot = min((t + 1) * BN + r, kclamp);
                uint32_t d = (uint32_t)((gcol >> 6) * KCH) + swzb(r, gcol & 63);
                size_t s = koff + (size_t)skidx[slot] * kD + gcol;
                CP_ASYNC16(kbn + d,           (const char*)(g_hi + s));
                CP_ASYNC16(kbn + 4 * KCH + d, (const char*)(g_lo + s));
            }
            CP_COMMIT();
        }

        // ---- S = Q.K^T for tile t ----
        float sfr[4][4];
#pragma unroll
        for (int j = 0; j < 4; ++j)
#pragma unroll
            for (int c = 0; c < 4; ++c) sfr[j][c] = 0.0f;

#pragma unroll
        for (int ks = 0; ks < 16; ++ks) {
            uint32_t ahi[4], alo2[4];
            {
                int dd = 16 * ks + a_dh;
                uint32_t qo = (uint32_t)((dd >> 6) * QCH) + swzb(a_row, dd & 63);
                ldsm4(ahi, al + OFF_QHI + qo);
                ldsm4(alo2, al + OFF_QLO + qo);
            }
            uint32_t bh[2][4], bl[2][4];
#pragma unroll
            for (int u = 0; u < 2; ++u) {
                int key = 16 * u + b_key;
                int dd  = 16 * ks + b_dh;
                uint32_t ko = (uint32_t)((dd >> 6) * KCH) + swzb(key, dd & 63);
                ldsm4(bh[u], kb + ko);
                ldsm4(bl[u], kb + 4 * KCH + ko);
            }
#pragma unroll
            for (int u = 0; u < 2; ++u) {
                mma16816(sfr[2 * u],     ahi, bh[u]);
                mma16816(sfr[2 * u + 1], ahi, bh[u] + 2);
            }
#pragma unroll
            for (int u = 0; u < 2; ++u) {
                mma16816(sfr[2 * u],     ahi, bl[u]);
                mma16816(sfr[2 * u + 1], ahi, bl[u] + 2);
            }
#pragma unroll
            for (int u = 0; u < 2; ++u) {
                mma16816(sfr[2 * u],     alo2, bh[u]);
                mma16816(sfr[2 * u + 1], alo2, bh[u] + 2);
            }
        }

        // ---- softmax(t): real keys all unmasked; pad slots -> p = 0 ----
        uint32_t phi[2][4], plo[2][4];
#pragma unroll
        for (int kp = 0; kp < 2; ++kp) {
#pragma unroll
            for (int jj = 0; jj < 2; ++jj) {
                int j  = 2 * kp + jj;
                int n0 = 8 * j + 2 * (lane & 3);
                int slot0 = t * BN + n0;
                float s0 = sfr[j][0], s1 = sfr[j][1], s2 = sfr[j][2], s3 = sfr[j][3];
                if (slot0 >= kcnt)     { s0 = -1e30f; s2 = -1e30f; }
                if (slot0 + 1 >= kcnt) { s1 = -1e30f; s3 = -1e30f; }
                float p0 = __expf(s0 - M0), p1 = __expf(s1 - M0);
                float p2 = __expf(s2 - M0), p3 = __expf(s3 - M0);
                lp0 += p0 + p1;
                lp1 += p2 + p3;
                __nv_bfloat162 h01 = __float22bfloat162_rn(make_float2(p0, p1));
                __nv_bfloat162 h23 = __float22bfloat162_rn(make_float2(p2, p3));
                float2 r01 = make_float2(p0 - __bfloat162float(h01.x),
                                         p1 - __bfloat162float(h01.y));
                float2 r23 = make_float2(p2 - __bfloat162float(h23.x),
                                         p3 - __bfloat162float(h23.y));
                __nv_bfloat162 l01 = __float22bfloat162_rn(r01);
                __nv_bfloat162 l23 = __float22bfloat162_rn(r23);
                phi[kp][2 * jj]     = *(uint32_t*)&h01;
                phi[kp][2 * jj + 1] = *(uint32_t*)&h23;
                plo[kp][2 * jj]     = *(uint32_t*)&l01;
                plo[kp][2 * jj + 1] = *(uint32_t*)&l23;
            }
        }

        // ---- O += P(t).V(t) ----
#pragma unroll
        for (int kp = 0; kp < 2; ++kp) {
#pragma unroll
            for (int dpp = 0; dpp < 8; ++dpp) {
                uint32_t vh[2][4], vl[2][4];
#pragma unroll
                for (int u = 0; u < 2; ++u) {
                    int key = 16 * kp + v_key;
                    int dd  = 16 * (2 * dpp + u) + v_dh;
                    uint32_t vo = (uint32_t)((dd >> 6) * KCH) + swzb(key, dd & 63);
                    ldsm4t(vh[u], kb + vo);
                    ldsm4t(vl[u], kb + 4 * KCH + vo);
                }
#pragma unroll
                for (int u = 0; u < 2; ++u) {
                    int o = 2 * (2 * dpp + u);
                    mma16816(oac[o],     phi[kp], vh[u]);
                    mma16816(oac[o + 1], phi[kp], vh[u] + 2);
                }
#pragma unroll
                for (int u = 0; u < 2; ++u) {
                    int o = 2 * (2 * dpp + u);
                    mma16816(oac[o],     phi[kp], vl[u]);
                    mma16816(oac[o + 1], phi[kp], vl[u] + 2);
                }
#pragma unroll
                for (int u = 0; u < 2; ++u) {
                    int o = 2 * (2 * dpp + u);
                    mma16816(oac[o],     plo[kp], vh[u]);
                    mma16816(oac[o + 1], plo[kp], vh[u] + 2);
                }
            }
        }
    }

    // ---- epilogue: masked-key correction + normalize + scatter ----
    lp0 += __shfl_xor_sync(0xffffffffu, lp0, 1);
    lp0 += __shfl_xor_sync(0xffffffffu, lp0, 2);
    lp1 += __shfl_xor_sync(0xffffffffu, lp1, 1);
    lp1 += __shfl_xor_sync(0xffffffffu, lp1, 2);

    const float cmask = __expf(MASK_FILL - M0);
    const float mcntf = (float)(kL - kcnt);
    const float inv0 = 1.0f / (lp0 + cmask * mcntf);
    const float inv1 = 1.0f / (lp1 + cmask * mcntf);
    const float* ms = g_msum + (size_t)kpb * kD;

    const int lr0 = 16 * w + (lane >> 2);
    const int lr1 = lr0 + 8;

    float* OB = out + ((size_t)pass * kB + b) * kL * kD;
    if (lr0 < nact) {
        float* O0 = OB + (size_t)rowmap[lr0] * kD;
#pragma unroll
        for (int nt = 0; nt < 32; ++nt) {
            int d = 8 * nt + 2 * (lane & 3);
            float2 m2 = *(const float2*)(ms + d);
            *(float2*)(O0 + d) = make_float2((oac[nt][0] + cmask * m2.x) * inv0,
                                             (oac[nt][1] + cmask * m2.y) * inv0);
        }
    }
    if (lr1 < nact) {
        float* O1 = OB + (size_t)rowmap[lr1] * kD;
#pragma unroll
        for (int nt = 0; nt < 32; ++nt) {
            int d = 8 * nt + 2 * (lane & 3);
            float2 m2 = *(const float2*)(ms + d);
            *(float2*)(O1 + d) = make_float2((oac[nt][2] + cmask * m2.x) * inv1,
                                             (oac[nt][3] + cmask * m2.y) * inv1);
        }
    }
}

extern "C" void kernel_launch(void* const* d_in, const int* in_sizes, int n_in,
                              void* d_out, int out_size) {
    (void)in_sizes; (void)n_in; (void)out_size;
    const float* v1  = (const float*)d_in[0];
    const void*  v1m = d_in[1];
    const float* v2  = (const float*)d_in[2];
    const void*  v2m = d_in[3];
    float* out = (float*)d_out;

    cudaFuncSetAttribute(fa_mma_kernel,
                         cudaFuncAttributeMaxDynamicSharedMemorySize, SMEM_BYTES);

    build_idx_kernel<<<2 * kB, 32>>>(v1m, v2m);
    cvt_kernel<<<2 * kB * 16, 256>>>(v1, v2);
    msum_zero_kernel<<<1024, 512>>>(v1, v2, out);
    dim3 grid(kL / BM, kB, 2);
    fa_mma_kernel<<<grid, 256, SMEM_BYTES>>>(out);
}